// round 16
// baseline (speedup 1.0000x reference)
#include <cuda_runtime.h>
#include <cuda_bf16.h>
#include <cstdint>

// Problem constants
#define B_      16
#define N_      8192
#define C_      6
#define K_      512      // NUM_GROUP
#define GS_     32       // GROUP_SIZE
#define BIGF    10000000000.0f
#define FINF    __int_as_float(0x7f800000)

// Output layout (float32, concatenated): neighborhood | center | nn_idx
#define NEIGH_ELEMS   (B_*K_*GS_*C_)   // 1,572,864
#define CENTER_ELEMS  (B_*K_*C_)       // 49,152
#define CENTER_OFF    (NEIGH_ELEMS)
#define NN_OFF        (NEIGH_ELEMS + CENTER_ELEMS)

typedef unsigned long long ull;

// Scratch (device globals; no allocation allowed)
__device__ int g_rep[B_ * K_];
__device__ __align__(16) float  g_x[B_ * N_];
__device__ __align__(16) float  g_y[B_ * N_];
__device__ __align__(16) float  g_z[B_ * N_];
__device__ __align__(16) float4 g_p4[B_ * N_];   // (x, y, z, |t|^2)

// Packed f32x2 ops (Blackwell sm_100+). Per-lane ops are exact rn fp32.
#define ADD2(o,a,b)   asm("add.rn.f32x2 %0, %1, %2;" : "=l"(o) : "l"(a), "l"(b))
#define MUL2(o,a,b)   asm("mul.rn.f32x2 %0, %1, %2;" : "=l"(o) : "l"(a), "l"(b))
#define FMA2(o,a,b,c) asm("fma.rn.f32x2 %0, %1, %2, %3;" : "=l"(o) : "l"(a), "l"(b), "l"(c))

__device__ __forceinline__ ull pk2(float lo, float hi) {
    return (ull)__float_as_uint(lo) | ((ull)__float_as_uint(hi) << 32);
}
__device__ __forceinline__ float plo(ull v) { return __uint_as_float((unsigned)v); }
__device__ __forceinline__ float phi(ull v) { return __uint_as_float((unsigned)(v >> 32)); }

// kNN key: (monotone-float-bits(d2) << 32) | idx. Exact lax.top_k order.
__device__ __forceinline__ ull mkkey(float d2, int j)
{
    int bb = __float_as_int(d2);
    unsigned u = (unsigned)bb ^ ((unsigned)(bb >> 31) | 0x80000000u);
    return ((ull)u << 32) | (unsigned)j;
}

// ---------------------------------------------------------------------------
// Kernel 0: AoS (stride 6) -> SoA xyz (FPS) + float4 (x,y,z,tt) (kNN).
// tt uses the exact rn chain of the reference.
// ---------------------------------------------------------------------------
__global__ void prep_kernel(const float* __restrict__ pc)
{
    int j = blockIdx.x * 256 + threadIdx.x;
    if (j >= B_ * N_) return;
    const float* p = pc + (size_t)j * C_;
    float px = p[0], py = p[1], pz = p[2];
    g_x[j] = px; g_y[j] = py; g_z[j] = pz;
    float tt = __fadd_rn(__fadd_rn(__fmul_rn(px, px), __fmul_rn(py, py)),
                         __fmul_rn(pz, pz));
    g_p4[j] = make_float4(px, py, pz, tt);
}

// ---------------------------------------------------------------------------
// Kernel 1: Farthest Point Sampling — R5-proven body; bv accumulation
// restructured as an exact max-tree (fmax is exactly associative: no
// rounding), shortening the serial dependence chain. One barrier/iter;
// per-warp candidates parity-double-buffered; winner coords re-fetched via
// same-address LDG broadcast. Exact reference numerics.
// ---------------------------------------------------------------------------
__global__ __launch_bounds__(512, 1)
void fps_kernel(int* __restrict__ rep)
{
    const int b = blockIdx.x, t = threadIdx.x;
    const int lane = t & 31, w = t >> 5;
    const int base = b * N_;

    float xs[16], ys[16], zs[16];
#pragma unroll
    for (int i = 0; i < 16; i++) {
        int j = base + t + i * 512;
        xs[i] = g_x[j]; ys[i] = g_y[j]; zs[i] = g_z[j];
    }
    ull xp[8], yp[8], zp[8];
#pragma unroll
    for (int p = 0; p < 8; p++) {
        xp[p] = pk2(xs[2*p], xs[2*p+1]);
        yp[p] = pk2(ys[2*p], ys[2*p+1]);
        zp[p] = pk2(zs[2*p], zs[2*p+1]);
    }
    float dst[16];
#pragma unroll
    for (int i = 0; i < 16; i++) dst[i] = BIGF;

    __shared__ unsigned sb[2][16];
    __shared__ unsigned si[2][16];

    float qx = g_x[base], qy = g_y[base], qz = g_z[base];
    int cur = 0;
    int* repb = rep + b * K_;

    for (int k = 0; k < K_; k++) {
        if (t == 0) repb[k] = cur;

        const ull nqx = pk2(-qx, -qx), nqy = pk2(-qy, -qy), nqz = pk2(-qz, -qz);
        float gm[8];
#pragma unroll
        for (int p = 0; p < 8; p++) {
            ull dx, dy, dz, s;
            ADD2(dx, xp[p], nqx);
            ADD2(dy, yp[p], nqy);
            ADD2(dz, zp[p], nqz);
            MUL2(dx, dx, dx);
            MUL2(dy, dy, dy);
            MUL2(dz, dz, dz);
            ADD2(s, dx, dy);
            ADD2(s, s, dz);
            float n0 = fminf(dst[2*p],   plo(s)); dst[2*p]   = n0;
            float n1 = fminf(dst[2*p+1], phi(s)); dst[2*p+1] = n1;
            gm[p] = fmaxf(n0, n1);
        }
        // exact max-tree (fmax associative, no rounding)
        float m0 = fmaxf(gm[0], gm[1]), m1 = fmaxf(gm[2], gm[3]);
        float m2 = fmaxf(gm[4], gm[5]), m3 = fmaxf(gm[6], gm[7]);
        const float bv = fmaxf(fmaxf(m0, m1), fmaxf(m2, m3));

        // warp argmax: max bits; matching lane(s) recover first-index by scan
        const unsigned mybits = __float_as_uint(bv);
        const unsigned mh = __reduce_max_sync(0xffffffffu, mybits);
        unsigned cnd = 0xffffffffu;
        if (mybits == mh) {
            int fi = 0;
#pragma unroll
            for (int i = 15; i >= 0; i--)
                if (__float_as_uint(dst[i]) == mybits) fi = i;   // smallest i wins
            cnd = (unsigned)(t + fi * 512);
        }
        const unsigned mi = __reduce_min_sync(0xffffffffu, cnd);

        const int par = k & 1;
        if (lane == 0) { sb[par][w] = mh; si[par][w] = mi; }
        __syncthreads();

        // all warps redundantly reduce the 16 per-warp candidates
        unsigned v  = (lane < 16) ? sb[par][lane] : 0u;
        unsigned i2 = (lane < 16) ? si[par][lane] : 0xffffffffu;
        unsigned Mh = __reduce_max_sync(0xffffffffu, v);
        unsigned c2 = (v == Mh) ? i2 : 0xffffffffu;
        unsigned Mi = __reduce_min_sync(0xffffffffu, c2);
        cur = (int)Mi;

        // broadcast-load winner coords (same address all lanes; L1 hit)
        qx = g_x[base + cur]; qy = g_y[base + cur]; qz = g_z[base + cur];
    }
}

// ---------------------------------------------------------------------------
// Kernel 2: kNN. 256-thread CTA, GC=8 centers (warp w <-> center w).
// Barrier-free main loop over private coalesced float4 streams. Distances
// packed per center-PAIR: d2 = (qq + fma-chain(-2q, p)) + tt — bit-identical
// to the reference (qq - 2*dot) + tt (power-of-2 scale commutes with rn).
// TOP-1 tracking per (thread, center): 3 ops/pair (FSETP+FSEL+SEL); strict <
// with increasing j preserves exact first-index ties. Selection: warp w over
// 256 candidates with redux-min rounds; every consumed candidate is refilled
// by an exact rescan (min key > consumed) of that thread's 32-point stream.
// Center gather folded in (reads g_rep, writes the center row).
// ---------------------------------------------------------------------------
#define GC 8

__global__ __launch_bounds__(256, 2)
void knn_kernel(const float* __restrict__ pc, const int* __restrict__ rep,
                float* __restrict__ out)
{
    __shared__ ull   cands[GC][256];
    __shared__ float scq[GC][3];
    __shared__ float sqq[GC];
    __shared__ int   scidx[GC];

    const int t = threadIdx.x, lane = t & 31, w = t >> 5;
    const int blk = blockIdx.x;
    const int b = blk >> 6;                 // 64 CTAs per batch (512/GC)
    const int cen0 = (blk & 63) * GC;
    const int bbase = b * N_;
    const float4* __restrict__ p4 = g_p4 + bbase;

    if (t < GC) {
        int idx = rep[b * K_ + cen0 + t];
        scidx[t] = idx;
        float4 P = p4[idx];
        scq[t][0] = P.x; scq[t][1] = P.y; scq[t][2] = P.z;
        sqq[t] = __fadd_rn(__fadd_rn(__fmul_rn(P.x, P.x), __fmul_rn(P.y, P.y)),
                           __fmul_rn(P.z, P.z));
    }
    __syncthreads();

    // packed per-center-pair constants: (-2*q of center 2pp, -2*q of 2pp+1)
    ull nqx2[4], nqy2[4], nqz2[4], qq2[4];
#pragma unroll
    for (int pp = 0; pp < 4; pp++) {
        nqx2[pp] = pk2(__fmul_rn(-2.0f, scq[2*pp][0]), __fmul_rn(-2.0f, scq[2*pp+1][0]));
        nqy2[pp] = pk2(__fmul_rn(-2.0f, scq[2*pp][1]), __fmul_rn(-2.0f, scq[2*pp+1][1]));
        nqz2[pp] = pk2(__fmul_rn(-2.0f, scq[2*pp][2]), __fmul_rn(-2.0f, scq[2*pp+1][2]));
        qq2[pp]  = pk2(sqq[2*pp], sqq[2*pp+1]);
    }

    float c0d[GC];
    int   c0i[GC];
#pragma unroll
    for (int c = 0; c < GC; c++) { c0d[c] = FINF; c0i[c] = 0x7fffffff; }

    // main loop: 32 points/thread, j strictly increasing, barrier-free
#pragma unroll 4
    for (int i = 0; i < 32; i++) {
        const int j = i * 256 + t;
        const float4 P = __ldg(p4 + j);
        const ull xx = pk2(P.x, P.x), yy = pk2(P.y, P.y);
        const ull zz = pk2(P.z, P.z), ww = pk2(P.w, P.w);
#pragma unroll
        for (int pp = 0; pp < 4; pp++) {
            ull nd, d;
            MUL2(nd, nqx2[pp], xx);
            FMA2(nd, nqy2[pp], yy, nd);
            FMA2(nd, nqz2[pp], zz, nd);    // nd = -2*dot (exact, per center)
            ADD2(d, qq2[pp], nd);          // qq - 2*dot
            ADD2(d, d, ww);                // + tt
            {   // center 2pp: top-1, strict < keeps first index
                const int c = 2 * pp;
                const float da = plo(d);
                const bool lt = da < c0d[c];
                c0d[c] = lt ? da : c0d[c];
                c0i[c] = lt ? j  : c0i[c];
            }
            {   // center 2pp+1
                const int c = 2 * pp + 1;
                const float db = phi(d);
                const bool lt = db < c0d[c];
                c0d[c] = lt ? db : c0d[c];
                c0i[c] = lt ? j  : c0i[c];
            }
        }
    }

#pragma unroll
    for (int c = 0; c < GC; c++) cands[c][t] = mkkey(c0d[c], c0i[c]);
    __syncthreads();

    // ---- selection: warp w -> center w; lane owns threads lane*8 + o ----
    const float qx = scq[w][0], qy = scq[w][1], qz = scq[w][2], qq = sqq[w];

    ull fr[GC];
#pragma unroll
    for (int o = 0; o < GC; o++) fr[o] = cands[w][lane * 8 + o];

    int selidx = 0;
    for (int r = 0; r < GS_; r++) {
        ull lm = fr[0]; int ow = 0;
#pragma unroll
        for (int o = 1; o < GC; o++) if (fr[o] < lm) { lm = fr[o]; ow = o; }

        unsigned hi  = (unsigned)(lm >> 32);
        unsigned mh  = __reduce_min_sync(0xffffffffu, hi);
        unsigned cnd = (hi == mh) ? (unsigned)lm : 0xffffffffu;
        unsigned mi  = __reduce_min_sync(0xffffffffu, cnd);
        if (lane == r) selidx = (int)mi;

        if (hi == mh && (unsigned)lm == mi) {  // this lane owned the winner
            const int T = lane * 8 + ow;
            // exact refill: min key strictly greater than the consumed key,
            // over thread T's private stream (j = m*256 + T)
            ull nv = ~0ull;
            const ull th = lm;
#pragma unroll 4
            for (int m = 0; m < 32; m++) {
                int j2 = m * 256 + T;
                float4 P = __ldg(p4 + j2);
                float dot = __fmaf_rn(qz, P.z, __fmaf_rn(qy, P.y, __fmul_rn(qx, P.x)));
                float d2  = __fadd_rn(__fsub_rn(qq, __fmul_rn(2.0f, dot)), P.w);
                ull key = mkkey(d2, j2);
                if (key > th && key < nv) nv = key;
            }
#pragma unroll
            for (int o = 0; o < GC; o++) if (o == ow) fr[o] = nv;
        }
    }

    // ---- output: lane L holds rank-L neighbor for center w ----
    const int gcen = b * K_ + cen0 + w;
    const int j = selidx;
    const float4 P = __ldg(p4 + j);
    const float* pf = pc + ((size_t)(bbase + j)) * C_;
    float* o6 = out + ((size_t)gcen * GS_ + lane) * C_;
    o6[0] = __fsub_rn(P.x, qx);
    o6[1] = __fsub_rn(P.y, qy);
    o6[2] = __fsub_rn(P.z, qz);
    o6[3] = pf[3];
    o6[4] = pf[4];
    o6[5] = pf[5];
    out[NN_OFF + (size_t)gcen * GS_ + lane] = (float)j;

    // center row (6 channels) for center w
    if (lane == 0) {
        const float* cf = pc + ((size_t)(bbase + scidx[w])) * C_;
        float* co = out + CENTER_OFF + (size_t)gcen * C_;
        co[0] = qx; co[1] = qy; co[2] = qz;
        co[3] = cf[3]; co[4] = cf[4]; co[5] = cf[5];
    }
}

// ---------------------------------------------------------------------------
extern "C" void kernel_launch(void* const* d_in, const int* in_sizes, int n_in,
                              void* d_out, int out_size)
{
    const float* pc = (const float*)d_in[0];
    float* out = (float*)d_out;

    int* rep = nullptr;
    cudaGetSymbolAddress((void**)&rep, g_rep);

    prep_kernel<<<(B_ * N_ + 255) / 256, 256>>>(pc);
    fps_kernel<<<B_, 512>>>(rep);
    knn_kernel<<<B_ * K_ / GC, 256>>>(pc, rep, out);
}

// round 17
// speedup vs baseline: 1.5626x; 1.5626x over previous
#include <cuda_runtime.h>
#include <cuda_bf16.h>
#include <cstdint>

// Problem constants
#define B_      16
#define N_      8192
#define C_      6
#define K_      512      // NUM_GROUP
#define GS_     32       // GROUP_SIZE
#define BIGF    10000000000.0f
#define FINF    __int_as_float(0x7f800000)

// Output layout (float32, concatenated): neighborhood | center | nn_idx
#define NEIGH_ELEMS   (B_*K_*GS_*C_)   // 1,572,864
#define CENTER_ELEMS  (B_*K_*C_)       // 49,152
#define CENTER_OFF    (NEIGH_ELEMS)
#define NN_OFF        (NEIGH_ELEMS + CENTER_ELEMS)

typedef unsigned long long ull;

// Scratch (device globals; no allocation allowed)
__device__ int g_rep[B_ * K_];
__device__ __align__(16) float  g_x[B_ * N_];
__device__ __align__(16) float  g_y[B_ * N_];
__device__ __align__(16) float  g_z[B_ * N_];
__device__ __align__(16) float4 g_p4[B_ * N_];   // (x, y, z, |t|^2)

// Packed f32x2 ops (Blackwell sm_100+). Per-lane ops are exact rn fp32.
#define ADD2(o,a,b)   asm("add.rn.f32x2 %0, %1, %2;" : "=l"(o) : "l"(a), "l"(b))
#define MUL2(o,a,b)   asm("mul.rn.f32x2 %0, %1, %2;" : "=l"(o) : "l"(a), "l"(b))
#define FMA2(o,a,b,c) asm("fma.rn.f32x2 %0, %1, %2, %3;" : "=l"(o) : "l"(a), "l"(b), "l"(c))

__device__ __forceinline__ ull pk2(float lo, float hi) {
    return (ull)__float_as_uint(lo) | ((ull)__float_as_uint(hi) << 32);
}
__device__ __forceinline__ float plo(ull v) { return __uint_as_float((unsigned)v); }
__device__ __forceinline__ float phi(ull v) { return __uint_as_float((unsigned)(v >> 32)); }

// kNN key (selection phase only): (monotone-float-bits(d2) << 32) | idx.
// Matches lax.top_k(-d2) exact order incl. first-index ties.
__device__ __forceinline__ ull mkkey(float d2, int j)
{
    int bb = __float_as_int(d2);
    unsigned u = (unsigned)bb ^ ((unsigned)(bb >> 31) | 0x80000000u);
    return ((ull)u << 32) | (unsigned)j;
}

// ---------------------------------------------------------------------------
// Kernel 0: AoS (stride 6) -> SoA xyz (FPS) + float4 (x,y,z,tt) (kNN).
// tt uses the exact rn chain of the reference.
// ---------------------------------------------------------------------------
__global__ void prep_kernel(const float* __restrict__ pc)
{
    int j = blockIdx.x * 256 + threadIdx.x;
    if (j >= B_ * N_) return;
    const float* p = pc + (size_t)j * C_;
    float px = p[0], py = p[1], pz = p[2];
    g_x[j] = px; g_y[j] = py; g_z[j] = pz;
    float tt = __fadd_rn(__fadd_rn(__fmul_rn(px, px), __fmul_rn(py, py)),
                         __fmul_rn(pz, pz));
    g_p4[j] = make_float4(px, py, pz, tt);
}

// ---------------------------------------------------------------------------
// Kernel 1: Farthest Point Sampling — R5/R10-proven body verbatim.
// One CTA/batch, 512 threads, 16 pts/thread (f32x2 packed). One barrier/iter;
// per-warp candidates parity-double-buffered; winner coords re-fetched via
// same-address LDG broadcast. Exact reference numerics.
// ---------------------------------------------------------------------------
__global__ __launch_bounds__(512, 1)
void fps_kernel(int* __restrict__ rep)
{
    const int b = blockIdx.x, t = threadIdx.x;
    const int lane = t & 31, w = t >> 5;
    const int base = b * N_;

    float xs[16], ys[16], zs[16];
#pragma unroll
    for (int i = 0; i < 16; i++) {
        int j = base + t + i * 512;
        xs[i] = g_x[j]; ys[i] = g_y[j]; zs[i] = g_z[j];
    }
    ull xp[8], yp[8], zp[8];
#pragma unroll
    for (int p = 0; p < 8; p++) {
        xp[p] = pk2(xs[2*p], xs[2*p+1]);
        yp[p] = pk2(ys[2*p], ys[2*p+1]);
        zp[p] = pk2(zs[2*p], zs[2*p+1]);
    }
    float dst[16];
#pragma unroll
    for (int i = 0; i < 16; i++) dst[i] = BIGF;

    __shared__ unsigned sb[2][16];
    __shared__ unsigned si[2][16];

    float qx = g_x[base], qy = g_y[base], qz = g_z[base];
    int cur = 0;
    int* repb = rep + b * K_;

    for (int k = 0; k < K_; k++) {
        if (t == 0) repb[k] = cur;

        const ull nqx = pk2(-qx, -qx), nqy = pk2(-qy, -qy), nqz = pk2(-qz, -qz);
        float bv = -1.0f;
#pragma unroll
        for (int p = 0; p < 8; p++) {
            ull dx, dy, dz, s;
            ADD2(dx, xp[p], nqx);
            ADD2(dy, yp[p], nqy);
            ADD2(dz, zp[p], nqz);
            MUL2(dx, dx, dx);
            MUL2(dy, dy, dy);
            MUL2(dz, dz, dz);
            ADD2(s, dx, dy);
            ADD2(s, s, dz);
            float n0 = fminf(dst[2*p],   plo(s)); dst[2*p]   = n0;
            float n1 = fminf(dst[2*p+1], phi(s)); dst[2*p+1] = n1;
            bv = fmaxf(bv, fmaxf(n0, n1));
        }

        // warp argmax: max bits; matching lane(s) recover first-index by scan
        const unsigned mybits = __float_as_uint(bv);
        const unsigned mh = __reduce_max_sync(0xffffffffu, mybits);
        unsigned cnd = 0xffffffffu;
        if (mybits == mh) {
            int fi = 0;
#pragma unroll
            for (int i = 15; i >= 0; i--)
                if (__float_as_uint(dst[i]) == mybits) fi = i;   // smallest i wins
            cnd = (unsigned)(t + fi * 512);
        }
        const unsigned mi = __reduce_min_sync(0xffffffffu, cnd);

        const int par = k & 1;
        if (lane == 0) { sb[par][w] = mh; si[par][w] = mi; }
        __syncthreads();

        // all warps redundantly reduce the 16 per-warp candidates
        unsigned v  = (lane < 16) ? sb[par][lane] : 0u;
        unsigned i2 = (lane < 16) ? si[par][lane] : 0xffffffffu;
        unsigned Mh = __reduce_max_sync(0xffffffffu, v);
        unsigned c2 = (v == Mh) ? i2 : 0xffffffffu;
        unsigned Mi = __reduce_min_sync(0xffffffffu, c2);
        cur = (int)Mi;

        // broadcast-load winner coords (same address all lanes; L1 hit)
        qx = g_x[base + cur]; qy = g_y[base + cur]; qz = g_z[base + cur];
    }
}

// ---------------------------------------------------------------------------
// Kernel 2: kNN — R10-proven body (top-2 branchless inserts + u64 selection
// with two-tier refill) + center gather folded in (reads rep, writes the
// 6-channel center row; center_kernel launch eliminated).
// 256-thread CTA, GC=8 centers (warp w <-> center w). Barrier-free main loop
// over private coalesced float4 streams; distances packed per center-PAIR:
// d2 = (qq + fma-chain(-2q, p)) + tt — bit-identical to the reference
// (qq - 2*dot) + tt (power-of-2 scale commutes with rn through mul/fma).
// ---------------------------------------------------------------------------
#define GC 8

__global__ __launch_bounds__(256, 2)
void knn_kernel(const float* __restrict__ pc, const int* __restrict__ rep,
                float* __restrict__ out)
{
    __shared__ ull   cands[GC][256][2];
    __shared__ float scq[GC][3];
    __shared__ float sqq[GC];
    __shared__ int   scidx[GC];

    const int t = threadIdx.x, lane = t & 31, w = t >> 5;
    const int blk = blockIdx.x;
    const int b = blk >> 6;                 // 64 CTAs per batch (512/GC)
    const int cen0 = (blk & 63) * GC;
    const int bbase = b * N_;
    const float4* __restrict__ p4 = g_p4 + bbase;

    if (t < GC) {
        int idx = rep[b * K_ + cen0 + t];
        scidx[t] = idx;
        float4 P = p4[idx];
        scq[t][0] = P.x; scq[t][1] = P.y; scq[t][2] = P.z;
        sqq[t] = __fadd_rn(__fadd_rn(__fmul_rn(P.x, P.x), __fmul_rn(P.y, P.y)),
                           __fmul_rn(P.z, P.z));
    }
    __syncthreads();

    // packed per-center-pair constants: (-2*q of center 2pp, -2*q of 2pp+1)
    ull nqx2[4], nqy2[4], nqz2[4], qq2[4];
#pragma unroll
    for (int pp = 0; pp < 4; pp++) {
        nqx2[pp] = pk2(__fmul_rn(-2.0f, scq[2*pp][0]), __fmul_rn(-2.0f, scq[2*pp+1][0]));
        nqy2[pp] = pk2(__fmul_rn(-2.0f, scq[2*pp][1]), __fmul_rn(-2.0f, scq[2*pp+1][1]));
        nqz2[pp] = pk2(__fmul_rn(-2.0f, scq[2*pp][2]), __fmul_rn(-2.0f, scq[2*pp+1][2]));
        qq2[pp]  = pk2(sqq[2*pp], sqq[2*pp+1]);
    }

    float c0d[GC], c1d[GC];
    int   c0i[GC], c1i[GC];
#pragma unroll
    for (int c = 0; c < GC; c++) {
        c0d[c] = FINF; c1d[c] = FINF; c0i[c] = 0x7fffffff; c1i[c] = 0x7fffffff;
    }

    // main loop: 32 points/thread, j strictly increasing, barrier-free
#pragma unroll 4
    for (int i = 0; i < 32; i++) {
        const int j = i * 256 + t;
        const float4 P = __ldg(p4 + j);
        const ull xx = pk2(P.x, P.x), yy = pk2(P.y, P.y);
        const ull zz = pk2(P.z, P.z), ww = pk2(P.w, P.w);
#pragma unroll
        for (int pp = 0; pp < 4; pp++) {
            ull nd, d;
            MUL2(nd, nqx2[pp], xx);
            FMA2(nd, nqy2[pp], yy, nd);
            FMA2(nd, nqz2[pp], zz, nd);    // nd = -2*dot (exact, per center)
            ADD2(d, qq2[pp], nd);          // qq - 2*dot
            ADD2(d, d, ww);                // + tt
            {   // center 2pp  (branchless sorted-insert; strict < = exact ties)
                const int c = 2 * pp;
                const float da = plo(d);
                const bool lt1 = da < c1d[c], lt0 = da < c0d[c];
                const float n1d = lt0 ? c0d[c] : (lt1 ? da : c1d[c]);
                const int   n1i = lt0 ? c0i[c] : (lt1 ? j  : c1i[c]);
                c0d[c] = lt0 ? da : c0d[c];
                c0i[c] = lt0 ? j  : c0i[c];
                c1d[c] = n1d; c1i[c] = n1i;
            }
            {   // center 2pp+1
                const int c = 2 * pp + 1;
                const float db = phi(d);
                const bool lt1 = db < c1d[c], lt0 = db < c0d[c];
                const float n1d = lt0 ? c0d[c] : (lt1 ? db : c1d[c]);
                const int   n1i = lt0 ? c0i[c] : (lt1 ? j  : c1i[c]);
                c0d[c] = lt0 ? db : c0d[c];
                c0i[c] = lt0 ? j  : c0i[c];
                c1d[c] = n1d; c1i[c] = n1i;
            }
        }
    }

#pragma unroll
    for (int c = 0; c < GC; c++) {
        cands[c][t][0] = mkkey(c0d[c], c0i[c]);
        cands[c][t][1] = mkkey(c1d[c], c1i[c]);
    }
    __syncthreads();

    // ---- selection: warp w -> center w; lane owns threads lane*8 + o ----
    const float qx = scq[w][0], qy = scq[w][1], qz = scq[w][2], qq = sqq[w];

    ull fr[GC];
    unsigned stmask = 0;                       // bit o: second candidate consumed
#pragma unroll
    for (int o = 0; o < GC; o++) fr[o] = cands[w][lane * 8 + o][0];

    int selidx = 0;
    for (int r = 0; r < GS_; r++) {
        ull lm = fr[0]; int ow = 0;
#pragma unroll
        for (int o = 1; o < GC; o++) if (fr[o] < lm) { lm = fr[o]; ow = o; }

        unsigned hi  = (unsigned)(lm >> 32);
        unsigned mh  = __reduce_min_sync(0xffffffffu, hi);
        unsigned cnd = (hi == mh) ? (unsigned)lm : 0xffffffffu;
        unsigned mi  = __reduce_min_sync(0xffffffffu, cnd);
        if (lane == r) selidx = (int)mi;

        if (hi == mh && (unsigned)lm == mi) {  // this lane owned the winner
            const int T = lane * 8 + ow;
            ull nv;
            if (!((stmask >> ow) & 1u)) {
                nv = cands[w][T][1];
                stmask |= 1u << ow;
            } else {
                // exact refill: min key strictly greater than last extracted,
                // over thread T's private stream (j = m*256 + T)
                nv = ~0ull;
                const ull th = lm;
#pragma unroll 4
                for (int m = 0; m < 32; m++) {
                    int j2 = m * 256 + T;
                    float4 P = __ldg(p4 + j2);
                    float dot = __fmaf_rn(qz, P.z, __fmaf_rn(qy, P.y, __fmul_rn(qx, P.x)));
                    float d2  = __fadd_rn(__fsub_rn(qq, __fmul_rn(2.0f, dot)), P.w);
                    ull key = mkkey(d2, j2);
                    if (key > th && key < nv) nv = key;
                }
            }
#pragma unroll
            for (int o = 0; o < GC; o++) if (o == ow) fr[o] = nv;
        }
    }

    // ---- output: lane L holds rank-L neighbor for center w ----
    const int gcen = b * K_ + cen0 + w;
    const int j = selidx;
    const float4 P = __ldg(p4 + j);
    const float* pf = pc + ((size_t)(bbase + j)) * C_;
    float* o6 = out + ((size_t)gcen * GS_ + lane) * C_;
    o6[0] = __fsub_rn(P.x, qx);
    o6[1] = __fsub_rn(P.y, qy);
    o6[2] = __fsub_rn(P.z, qz);
    o6[3] = pf[3];
    o6[4] = pf[4];
    o6[5] = pf[5];
    out[NN_OFF + (size_t)gcen * GS_ + lane] = (float)j;

    // center row (6 channels) for center w
    if (lane == 0) {
        const float* cf = pc + ((size_t)(bbase + scidx[w])) * C_;
        float* co = out + CENTER_OFF + (size_t)gcen * C_;
        co[0] = qx; co[1] = qy; co[2] = qz;
        co[3] = cf[3]; co[4] = cf[4]; co[5] = cf[5];
    }
}

// ---------------------------------------------------------------------------
extern "C" void kernel_launch(void* const* d_in, const int* in_sizes, int n_in,
                              void* d_out, int out_size)
{
    const float* pc = (const float*)d_in[0];
    float* out = (float*)d_out;

    int* rep = nullptr;
    cudaGetSymbolAddress((void**)&rep, g_rep);

    prep_kernel<<<(B_ * N_ + 255) / 256, 256>>>(pc);
    fps_kernel<<<B_, 512>>>(rep);
    knn_kernel<<<B_ * K_ / GC, 256>>>(pc, rep, out);
}